// round 7
// baseline (speedup 1.0000x reference)
#include <cuda_runtime.h>
#include <cstdint>

// ---------------------------------------------------------------------------
// SelfAttention B=4, T=2048, D=1024, causal — fused-softmax tf32 edition.
//   Proj: Q = X Wq^T / 32 ; K = X Wk^T ; Vt = (X Wv^T)^T  (one launch, bz 0/1/2)
//         (X, W rounded to tf32 in-fragment; Q/K/Vt tf32-rounded in epilogue)
//   S-GEMM (causal tiles): writes P_t = exp(S - m_tile) (masked to 0), plus
//         per-(row, tile) partials (m_tile, l_tile) for the softmax merge.
//   PV-GEMM: prologue merges partials -> per-(row,tile) scale; A fragments are
//         scaled + tf32-rounded in registers. out = P V.
// GEMM core: 128x128x32 tiles, 3-stage cp.async, XOR-swizzled smem,
// ldmatrix.x4.b16 operand fetch, m16n8k8 tf32 MMA, 8 warps, 2 CTAs/SM.
// ---------------------------------------------------------------------------

namespace {
constexpr int BATCH = 4;
constexpr int T     = 2048;
constexpr int D     = 1024;
constexpr int MQKV  = BATCH * T;          // 8192
constexpr int NTILE = T / 128;            // 16 column tiles per row

constexpr int BM = 128, BN = 128, BK = 32;   // BK floats = 128 B rows
constexpr int STG = 3;                        // pipeline stages
constexpr int NT  = 256;                      // 8 warps

constexpr int A_STG = BM * 128;               // 16384 B
constexpr int B_STG = BN * 128;               // 16384 B
constexpr int STG_BYTES = A_STG + B_STG;      // 32768 B
constexpr int SMEM_TOTAL = STG * STG_BYTES;   // 98304 B
}

// scratch (device globals — allocation-free)
__device__ float g_Q [(size_t)MQKV * D];
__device__ float g_K [(size_t)MQKV * D];
__device__ float g_Vt[(size_t)D * MQKV];                  // V transposed [D][B*T]
__device__ float g_S [(size_t)BATCH * T * T];             // P_t = exp(S - m_tile)
__device__ float g_pm[(size_t)BATCH * T * NTILE];         // per-tile row max
__device__ float g_pl[(size_t)BATCH * T * NTILE];         // per-tile row sumexp

// ---------------------------------------------------------------------------
// helpers
// ---------------------------------------------------------------------------
__device__ __forceinline__ unsigned f2tf(float x) {
    unsigned r; asm("cvt.rna.tf32.f32 %0, %1;" : "=r"(r) : "f"(x)); return r;
}
__device__ __forceinline__ float tf32r(float x) { return __uint_as_float(f2tf(x)); }
__device__ __forceinline__ uint32_t tfu(uint32_t bits) {   // round fp32 bits -> tf32 bits
    return f2tf(__uint_as_float(bits));
}

__device__ __forceinline__ uint32_t smem_u32(const void* p) {
    uint32_t a;
    asm("{ .reg .u64 t; cvta.to.shared.u64 t, %1; cvt.u32.u64 %0, t; }" : "=r"(a) : "l"(p));
    return a;
}

__device__ __forceinline__ void cp16s(uint32_t s, const void* g) {
    asm volatile("cp.async.cg.shared.global [%0], [%1], 16;" ::"r"(s), "l"(g));
}
__device__ __forceinline__ void cp_commit() { asm volatile("cp.async.commit_group;"); }
__device__ __forceinline__ void cp_wait1()  { asm volatile("cp.async.wait_group 1;"); }

__device__ __forceinline__ void ldsm4(uint32_t& r0, uint32_t& r1, uint32_t& r2,
                                      uint32_t& r3, uint32_t addr) {
    asm volatile("ldmatrix.sync.aligned.m8n8.x4.shared.b16 {%0,%1,%2,%3}, [%4];"
                 : "=r"(r0), "=r"(r1), "=r"(r2), "=r"(r3) : "r"(addr));
}

__device__ __forceinline__ void mma8(float* c, const uint32_t* a, const uint32_t* b) {
    asm volatile(
        "mma.sync.aligned.m16n8k8.row.col.f32.tf32.tf32.f32 "
        "{%0,%1,%2,%3}, {%4,%5,%6,%7}, {%8,%9}, {%0,%1,%2,%3};"
        : "+f"(c[0]), "+f"(c[1]), "+f"(c[2]), "+f"(c[3])
        : "r"(a[0]), "r"(a[1]), "r"(a[2]), "r"(a[3]), "r"(b[0]), "r"(b[1]));
}

// ---------------------------------------------------------------------------
// TN GEMM:  C[m,n] = sum_k A[m,k] * B[n,k]   (both K-major)
//   MODE 0: S = QK^T, causal tile skip; epilogue: exp + stats
//   MODE 1: out = P Vt^T, causal K extent; prologue: merge stats -> A scaling
//   MODE 2: QKV projection, in-fragment tf32 rounding of X/W; bz routes output
// ---------------------------------------------------------------------------
template <int MODE>
__global__ void __launch_bounds__(NT, 2)
tc_gemm(const float* __restrict__ A,
        const float* __restrict__ B0, const float* __restrict__ B1,
        const float* __restrict__ B2,
        float* __restrict__ C0, float* __restrict__ C1, float* __restrict__ C2,
        float* __restrict__ pm, float* __restrict__ pl,
        int K, int lda, int ldb, int ldc,
        long long sA, long long sB, long long sC) {
    const int bx = blockIdx.x, by = blockIdx.y, bz = blockIdx.z;
    if (MODE == 0 && bx > by) return;            // causal tile skip
    if (MODE == 1) K = (by + 1) * BM;            // causal K extent

    extern __shared__ char smem[];
    const uint32_t sb = smem_u32(smem);
    // static shared scratch: MODE 1 -> scale[16][128]; MODE 0 -> red[4][128]+srow
    __shared__ float saux[NTILE * 128];
    __shared__ float srow[128];

    const int tid = threadIdx.x, w = tid >> 5, lane = tid & 31;
    const int wm = w >> 2, wn = w & 3;           // 2 x 4 warps, 64x32 each

    const float* Bsel = (MODE == 2) ? (bz == 0 ? B0 : bz == 1 ? B1 : B2) : B0;
    const float* Ab = A + (size_t)bz * sA + (size_t)by * BM * lda;
    const float* Bb = Bsel + (size_t)bz * sB + (size_t)bx * BN * ldb;

    // cp.async per-thread pattern
    const int cr = tid >> 3, cc = tid & 7;
    const uint32_t c_sw = (uint32_t)(cc * 16) ^ ((uint32_t)(cr & 7) << 4);

    // ldmatrix per-lane geometry
    const int l7 = lane & 7, lb3 = (lane >> 3) & 1, lb4 = (lane >> 4) & 1;
    const uint32_t xr = (uint32_t)l7 << 4;
    const uint32_t aRow0 = (uint32_t)(wm * 64 + lb3 * 8 + l7) * 128;
    const uint32_t aSeg  = (uint32_t)lb4 * 16;
    const uint32_t bRow0 = (uint32_t)(wn * 32 + lb4 * 8 + l7) * 128;
    const uint32_t bSeg  = (uint32_t)lb3 * 16;

    float acc[4][4][4];
#pragma unroll
    for (int i = 0; i < 4; i++)
#pragma unroll
        for (int j = 0; j < 4; j++)
#pragma unroll
            for (int k = 0; k < 4; k++) acc[i][j][k] = 0.f;

    auto ldst = [&](int slot, int kt) {
        const uint32_t stg = sb + slot * STG_BYTES;
        const float* ag = Ab + kt * BK;
#pragma unroll
        for (int i = 0; i < 4; i++) {
            int r = cr + i * 32;
            cp16s(stg + (uint32_t)r * 128 + c_sw, ag + (size_t)r * lda + cc * 4);
        }
        const float* bg = Bb + kt * BK;
#pragma unroll
        for (int i = 0; i < 4; i++) {
            int r = cr + i * 32;
            cp16s(stg + A_STG + (uint32_t)r * 128 + c_sw, bg + (size_t)r * ldb + cc * 4);
        }
    };

    const int nkt = K / BK;
    ldst(0, 0); cp_commit();
    if (nkt > 1) ldst(1, 1);
    cp_commit();

    // ---- MODE 1 prologue: merge per-tile softmax partials -> scale table ----
    if (MODE == 1) {
        if (tid < 128) {
            const int q = by * BM + tid;
            const float* pmr = pm + ((size_t)bz * T + q) * NTILE;
            const float* plr = pl + ((size_t)bz * T + q) * NTILE;
            float m = -3.4e38f;
            for (int tx = 0; tx <= by; tx++) m = fmaxf(m, pmr[tx]);
            float l = 0.f;
            for (int tx = 0; tx <= by; tx++) l += plr[tx] * __expf(pmr[tx] - m);
            const float il = 1.f / l;
            for (int tx = 0; tx <= by; tx++)
                saux[tx * 128 + tid] = __expf(pmr[tx] - m) * il;
        }
        __syncthreads();
    }

    int slot = 0;
    for (int kt = 0; kt < nkt; kt++) {
        cp_wait1();
        __syncthreads();
        if (kt + 2 < nkt) {
            int ns = slot + 2; if (ns >= STG) ns -= STG;
            ldst(ns, kt + 2);
        }
        cp_commit();

        const uint32_t astg = sb + slot * STG_BYTES;
        const uint32_t bstg = astg + A_STG;
        const int tx = kt >> 2;                     // 128-wide source tile (MODE 1)
#pragma unroll
        for (int kk4 = 0; kk4 < 128; kk4 += 32) {
            uint32_t af[4][4], bf[4][2];
            const uint32_t aoff = ((uint32_t)kk4 | aSeg) ^ xr;
            const uint32_t boff = ((uint32_t)kk4 | bSeg) ^ xr;
#pragma unroll
            for (int mi = 0; mi < 4; mi++) {
                ldsm4(af[mi][0], af[mi][1], af[mi][2], af[mi][3],
                      astg + aRow0 + (uint32_t)mi * 2048 + aoff);
                if (MODE == 2) {
#pragma unroll
                    for (int t = 0; t < 4; t++) af[mi][t] = tfu(af[mi][t]);
                } else if (MODE == 1) {
                    // regs {0,2}: row base+lane>>2 ; regs {1,3}: +8
                    const int ar = wm * 64 + mi * 16 + (lane >> 2);
                    const float slo = saux[tx * 128 + ar];
                    const float shi = saux[tx * 128 + ar + 8];
                    af[mi][0] = f2tf(__uint_as_float(af[mi][0]) * slo);
                    af[mi][2] = f2tf(__uint_as_float(af[mi][2]) * slo);
                    af[mi][1] = f2tf(__uint_as_float(af[mi][1]) * shi);
                    af[mi][3] = f2tf(__uint_as_float(af[mi][3]) * shi);
                }
            }
#pragma unroll
            for (int nj = 0; nj < 2; nj++) {
                uint32_t r0, r1, r2, r3;
                ldsm4(r0, r1, r2, r3, bstg + bRow0 + (uint32_t)nj * 2048 + boff);
                if (MODE == 2) { r0 = tfu(r0); r1 = tfu(r1); r2 = tfu(r2); r3 = tfu(r3); }
                bf[nj * 2][0] = r0; bf[nj * 2][1] = r1;
                bf[nj * 2 + 1][0] = r2; bf[nj * 2 + 1][1] = r3;
            }
#pragma unroll
            for (int mi = 0; mi < 4; mi++)
#pragma unroll
                for (int ni = 0; ni < 4; ni++) mma8(acc[mi][ni], af[mi], bf[ni]);
        }
        __syncthreads();
        if (++slot == STG) slot = 0;
    }

    // ---- MODE 0 epilogue: per-row tile max / sumexp, exp-transform acc ----
    if (MODE == 0) {
        float* red = saux;                         // [4][128]
        const bool diag = (bx == by);
        // phase 1: masked per-thread row max over this warp's 8 cols
#pragma unroll
        for (int mi = 0; mi < 4; mi++) {
#pragma unroll
            for (int h = 0; h < 2; h++) {
                const int r = wm * 64 + mi * 16 + (lane >> 2) + 8 * h;
                float mx = -3.4e38f;
#pragma unroll
                for (int ni = 0; ni < 4; ni++) {
#pragma unroll
                    for (int c2 = 0; c2 < 2; c2++) {
                        const int c = wn * 32 + ni * 8 + ((lane & 3) << 1) + c2;
                        const bool ok = !diag || (c <= r);
                        if (ok) mx = fmaxf(mx, acc[mi][ni][2 * h + c2]);
                    }
                }
                mx = fmaxf(mx, __shfl_xor_sync(0xffffffffu, mx, 1));
                mx = fmaxf(mx, __shfl_xor_sync(0xffffffffu, mx, 2));
                if ((lane & 3) == 0) red[wn * 128 + r] = mx;
            }
        }
        __syncthreads();
        if (tid < 128)
            srow[tid] = fmaxf(fmaxf(red[tid], red[128 + tid]),
                              fmaxf(red[256 + tid], red[384 + tid]));
        __syncthreads();
        // phase 2: exp (in place) + per-thread row sums
#pragma unroll
        for (int mi = 0; mi < 4; mi++) {
#pragma unroll
            for (int h = 0; h < 2; h++) {
                const int r = wm * 64 + mi * 16 + (lane >> 2) + 8 * h;
                const float m = srow[r];
                float sum = 0.f;
#pragma unroll
                for (int ni = 0; ni < 4; ni++) {
#pragma unroll
                    for (int c2 = 0; c2 < 2; c2++) {
                        const int c = wn * 32 + ni * 8 + ((lane & 3) << 1) + c2;
                        const bool ok = !diag || (c <= r);
                        const float e = ok ? __expf(acc[mi][ni][2 * h + c2] - m) : 0.f;
                        acc[mi][ni][2 * h + c2] = e;
                        sum += e;
                    }
                }
                sum += __shfl_xor_sync(0xffffffffu, sum, 1);
                sum += __shfl_xor_sync(0xffffffffu, sum, 2);
                if ((lane & 3) == 0) red[wn * 128 + r] = sum;
            }
        }
        __syncthreads();
        if (tid < 128) {
            const float l = red[tid] + red[128 + tid] + red[256 + tid] + red[384 + tid];
            const int q = by * BM + tid;
            pm[((size_t)bz * T + q) * NTILE + bx] = srow[tid];
            pl[((size_t)bz * T + q) * NTILE + bx] = l;
        }
    }

    // ---- store ----
#pragma unroll
    for (int mi = 0; mi < 4; mi++) {
#pragma unroll
        for (int ni = 0; ni < 4; ni++) {
            const int row = by * BM + wm * 64 + mi * 16 + (lane >> 2);
            const int col = bx * BN + wn * 32 + ni * 8 + ((lane & 3) << 1);
            float v0 = acc[mi][ni][0], v1 = acc[mi][ni][1];
            float v2 = acc[mi][ni][2], v3 = acc[mi][ni][3];
            if (MODE == 2) {
                if (bz == 0) { v0 *= 0.03125f; v1 *= 0.03125f; v2 *= 0.03125f; v3 *= 0.03125f; }
                v0 = tf32r(v0); v1 = tf32r(v1); v2 = tf32r(v2); v3 = tf32r(v3);
                if (bz == 2) {   // Vt: [D][MQKV], transposed store
                    C2[(size_t)col * MQKV + row]           = v0;
                    C2[(size_t)(col + 1) * MQKV + row]     = v1;
                    C2[(size_t)col * MQKV + row + 8]       = v2;
                    C2[(size_t)(col + 1) * MQKV + row + 8] = v3;
                } else {
                    float* Cd = (bz == 0) ? C0 : C1;
                    *reinterpret_cast<float2*>(Cd + (size_t)row * ldc + col) = make_float2(v0, v1);
                    *reinterpret_cast<float2*>(Cd + (size_t)(row + 8) * ldc + col) = make_float2(v2, v3);
                }
            } else {
                float* Cd = C0 + (size_t)bz * sC;
                *reinterpret_cast<float2*>(Cd + (size_t)row * ldc + col) = make_float2(v0, v1);
                *reinterpret_cast<float2*>(Cd + (size_t)(row + 8) * ldc + col) = make_float2(v2, v3);
            }
        }
    }
}

// ---------------------------------------------------------------------------
// launch
// ---------------------------------------------------------------------------
extern "C" void kernel_launch(void* const* d_in, const int* in_sizes, int n_in,
                              void* d_out, int out_size) {
    const float* X  = (const float*)d_in[0];
    const float* Wq = (const float*)d_in[1];
    const float* Wk = (const float*)d_in[2];
    const float* Wv = (const float*)d_in[3];
    float* out = (float*)d_out;

    float *Qp, *Kp, *Vtp, *Sp, *pmp, *plp;
    cudaGetSymbolAddress((void**)&Qp, g_Q);
    cudaGetSymbolAddress((void**)&Kp, g_K);
    cudaGetSymbolAddress((void**)&Vtp, g_Vt);
    cudaGetSymbolAddress((void**)&Sp, g_S);
    cudaGetSymbolAddress((void**)&pmp, g_pm);
    cudaGetSymbolAddress((void**)&plp, g_pl);

    cudaFuncSetAttribute(tc_gemm<0>, cudaFuncAttributeMaxDynamicSharedMemorySize, SMEM_TOTAL);
    cudaFuncSetAttribute(tc_gemm<1>, cudaFuncAttributeMaxDynamicSharedMemorySize, SMEM_TOTAL);
    cudaFuncSetAttribute(tc_gemm<2>, cudaFuncAttributeMaxDynamicSharedMemorySize, SMEM_TOTAL);

    // QKV projections (bz = 0:Q, 1:K, 2:Vt); X/W rounded in-fragment
    dim3 gp(D / BN, MQKV / BM, 3);
    tc_gemm<2><<<gp, NT, SMEM_TOTAL>>>(
        X, Wq, Wk, Wv, Qp, Kp, Vtp, nullptr, nullptr,
        D, D, D, D, 0, 0, 0);

    // S tiles: P_t = exp(QK^T - m_tile), partial stats
    dim3 gs(T / BN, T / BM, BATCH);
    tc_gemm<0><<<gs, NT, SMEM_TOTAL>>>(
        Qp, Kp, nullptr, nullptr, Sp, nullptr, nullptr, pmp, plp,
        D, D, D, T,
        (long long)T * D, (long long)T * D, (long long)T * T);

    // out = P V  (A fragments scaled by merged softmax factors)
    dim3 gv(D / BN, T / BM, BATCH);
    tc_gemm<1><<<gv, NT, SMEM_TOTAL>>>(
        Sp, Vtp, nullptr, nullptr, out, nullptr, nullptr, pmp, plp,
        T, T, MQKV, D,
        (long long)T * T, (long long)T, (long long)T * D);
}

// round 9
// speedup vs baseline: 1.1353x; 1.1353x over previous
#include <cuda_runtime.h>
#include <cstdint>

// ---------------------------------------------------------------------------
// SelfAttention B=4, T=2048, D=1024, causal — fused-exp tf32 edition v2.
//   round(X), round(W) -> tf32-exact operands (tiny elementwise kernels)
//   Proj: Q = Xr Wq^T / 32 ; K = Xr Wk^T ; Vt = (Xr Wv^T)^T (one launch, pure GEMM)
//   S-GEMM (causal tiles): P_t = exp(S - m_tile) in-place epilogue + (m,l) partials
//   Rescale: merge partials per row; P *= exp(m_t - m)/l, tf32-round (mem-bound)
//   PV-GEMM: pure GEMM, causal K extent. out = P V.
// GEMM core: 128x128x32 tiles, 3-stage cp.async, XOR-swizzled smem,
// ldmatrix.x4.b16 operand fetch, m16n8k8 tf32 MMA, 8 warps, 2 CTAs/SM.
// ---------------------------------------------------------------------------

namespace {
constexpr int BATCH = 4;
constexpr int T     = 2048;
constexpr int D     = 1024;
constexpr int MQKV  = BATCH * T;          // 8192
constexpr int NTILE = T / 128;            // 16 column tiles per row

constexpr int BM = 128, BN = 128, BK = 32;   // BK floats = 128 B rows
constexpr int STG = 3;                        // pipeline stages
constexpr int NT  = 256;                      // 8 warps

constexpr int A_STG = BM * 128;               // 16384 B
constexpr int B_STG = BN * 128;               // 16384 B
constexpr int STG_BYTES = A_STG + B_STG;      // 32768 B
constexpr int SMEM_TOTAL = STG * STG_BYTES;   // 98304 B
}

// scratch (device globals — allocation-free)
__device__ float g_Xr[(size_t)MQKV * D];
__device__ float g_Wq[(size_t)D * D];
__device__ float g_Wk[(size_t)D * D];
__device__ float g_Wv[(size_t)D * D];
__device__ float g_Q [(size_t)MQKV * D];
__device__ float g_K [(size_t)MQKV * D];
__device__ float g_Vt[(size_t)D * MQKV];                  // V transposed [D][B*T]
__device__ float g_S [(size_t)BATCH * T * T];             // P_t = exp(S - m_tile)
__device__ float g_pm[(size_t)BATCH * T * NTILE];         // per-tile row max
__device__ float g_pl[(size_t)BATCH * T * NTILE];         // per-tile row sumexp

// ---------------------------------------------------------------------------
// helpers
// ---------------------------------------------------------------------------
__device__ __forceinline__ unsigned f2tf(float x) {
    unsigned r; asm("cvt.rna.tf32.f32 %0, %1;" : "=r"(r) : "f"(x)); return r;
}
__device__ __forceinline__ float tf32r(float x) { return __uint_as_float(f2tf(x)); }

__device__ __forceinline__ uint32_t smem_u32(const void* p) {
    uint32_t a;
    asm("{ .reg .u64 t; cvta.to.shared.u64 t, %1; cvt.u32.u64 %0, t; }" : "=r"(a) : "l"(p));
    return a;
}

__device__ __forceinline__ void cp16s(uint32_t s, const void* g) {
    asm volatile("cp.async.cg.shared.global [%0], [%1], 16;" ::"r"(s), "l"(g));
}
__device__ __forceinline__ void cp_commit() { asm volatile("cp.async.commit_group;"); }
__device__ __forceinline__ void cp_wait1()  { asm volatile("cp.async.wait_group 1;"); }

__device__ __forceinline__ void ldsm4(uint32_t& r0, uint32_t& r1, uint32_t& r2,
                                      uint32_t& r3, uint32_t addr) {
    asm volatile("ldmatrix.sync.aligned.m8n8.x4.shared.b16 {%0,%1,%2,%3}, [%4];"
                 : "=r"(r0), "=r"(r1), "=r"(r2), "=r"(r3) : "r"(addr));
}

__device__ __forceinline__ void mma8(float* c, const uint32_t* a, const uint32_t* b) {
    asm volatile(
        "mma.sync.aligned.m16n8k8.row.col.f32.tf32.tf32.f32 "
        "{%0,%1,%2,%3}, {%4,%5,%6,%7}, {%8,%9}, {%0,%1,%2,%3};"
        : "+f"(c[0]), "+f"(c[1]), "+f"(c[2]), "+f"(c[3])
        : "r"(a[0]), "r"(a[1]), "r"(a[2]), "r"(a[3]), "r"(b[0]), "r"(b[1]));
}

// ---------------------------------------------------------------------------
// TN GEMM:  C[m,n] = sum_k A[m,k] * B[n,k]   (both K-major)
//   MODE 0: S = QK^T, causal tile skip; epilogue: exp + (m,l) partials
//   MODE 1: out = P Vt^T, causal K extent; pure GEMM
//   MODE 2: QKV projection (pre-rounded inputs); bz routes output; epilogue tf32
// ---------------------------------------------------------------------------
template <int MODE>
__global__ void __launch_bounds__(NT, 2)
tc_gemm(const float* __restrict__ A,
        const float* __restrict__ B0, const float* __restrict__ B1,
        const float* __restrict__ B2,
        float* __restrict__ C0, float* __restrict__ C1, float* __restrict__ C2,
        float* __restrict__ pm, float* __restrict__ pl,
        int K, int lda, int ldb, int ldc,
        long long sA, long long sB, long long sC) {
    const int bx = blockIdx.x, by = blockIdx.y, bz = blockIdx.z;
    if (MODE == 0 && bx > by) return;            // causal tile skip
    if (MODE == 1) K = (by + 1) * BM;            // causal K extent

    extern __shared__ char smem[];
    const uint32_t sb = smem_u32(smem);
    __shared__ float red[4 * 128];               // MODE 0 reductions
    __shared__ float srow[128];

    const int tid = threadIdx.x, w = tid >> 5, lane = tid & 31;
    const int wm = w >> 2, wn = w & 3;           // 2 x 4 warps, 64x32 each

    const float* Bsel = (MODE == 2) ? (bz == 0 ? B0 : bz == 1 ? B1 : B2) : B0;
    const float* Ab = A + (size_t)bz * sA + (size_t)by * BM * lda;
    const float* Bb = Bsel + (size_t)bz * sB + (size_t)bx * BN * ldb;

    // cp.async per-thread pattern
    const int cr = tid >> 3, cc = tid & 7;
    const uint32_t c_sw = (uint32_t)(cc * 16) ^ ((uint32_t)(cr & 7) << 4);

    // ldmatrix per-lane geometry
    const int l7 = lane & 7, lb3 = (lane >> 3) & 1, lb4 = (lane >> 4) & 1;
    const uint32_t xr = (uint32_t)l7 << 4;
    const uint32_t aRow0 = (uint32_t)(wm * 64 + lb3 * 8 + l7) * 128;
    const uint32_t aSeg  = (uint32_t)lb4 * 16;
    const uint32_t bRow0 = (uint32_t)(wn * 32 + lb4 * 8 + l7) * 128;
    const uint32_t bSeg  = (uint32_t)lb3 * 16;

    float acc[4][4][4];
#pragma unroll
    for (int i = 0; i < 4; i++)
#pragma unroll
        for (int j = 0; j < 4; j++)
#pragma unroll
            for (int k = 0; k < 4; k++) acc[i][j][k] = 0.f;

    auto ldst = [&](int slot, int kt) {
        const uint32_t stg = sb + slot * STG_BYTES;
        const float* ag = Ab + kt * BK;
#pragma unroll
        for (int i = 0; i < 4; i++) {
            int r = cr + i * 32;
            cp16s(stg + (uint32_t)r * 128 + c_sw, ag + (size_t)r * lda + cc * 4);
        }
        const float* bg = Bb + kt * BK;
#pragma unroll
        for (int i = 0; i < 4; i++) {
            int r = cr + i * 32;
            cp16s(stg + A_STG + (uint32_t)r * 128 + c_sw, bg + (size_t)r * ldb + cc * 4);
        }
    };

    const int nkt = K / BK;
    ldst(0, 0); cp_commit();
    if (nkt > 1) ldst(1, 1);
    cp_commit();

    int slot = 0;
    for (int kt = 0; kt < nkt; kt++) {
        cp_wait1();
        __syncthreads();
        if (kt + 2 < nkt) {
            int ns = slot + 2; if (ns >= STG) ns -= STG;
            ldst(ns, kt + 2);
        }
        cp_commit();

        const uint32_t astg = sb + slot * STG_BYTES;
        const uint32_t bstg = astg + A_STG;
#pragma unroll
        for (int kk4 = 0; kk4 < 128; kk4 += 32) {
            uint32_t af[4][4], bf[4][2];
            const uint32_t aoff = ((uint32_t)kk4 | aSeg) ^ xr;
            const uint32_t boff = ((uint32_t)kk4 | bSeg) ^ xr;
#pragma unroll
            for (int mi = 0; mi < 4; mi++)
                ldsm4(af[mi][0], af[mi][1], af[mi][2], af[mi][3],
                      astg + aRow0 + (uint32_t)mi * 2048 + aoff);
#pragma unroll
            for (int nj = 0; nj < 2; nj++) {
                uint32_t r0, r1, r2, r3;
                ldsm4(r0, r1, r2, r3, bstg + bRow0 + (uint32_t)nj * 2048 + boff);
                bf[nj * 2][0] = r0; bf[nj * 2][1] = r1;
                bf[nj * 2 + 1][0] = r2; bf[nj * 2 + 1][1] = r3;
            }
#pragma unroll
            for (int mi = 0; mi < 4; mi++)
#pragma unroll
                for (int ni = 0; ni < 4; ni++) mma8(acc[mi][ni], af[mi], bf[ni]);
        }
        __syncthreads();
        if (++slot == STG) slot = 0;
    }

    // ---- MODE 0 epilogue: per-row tile max / sumexp, exp-transform acc ----
    if (MODE == 0) {
        const bool diag = (bx == by);
#pragma unroll
        for (int mi = 0; mi < 4; mi++) {
#pragma unroll
            for (int h = 0; h < 2; h++) {
                const int r = wm * 64 + mi * 16 + (lane >> 2) + 8 * h;
                float mx = -3.4e38f;
#pragma unroll
                for (int ni = 0; ni < 4; ni++) {
#pragma unroll
                    for (int c2 = 0; c2 < 2; c2++) {
                        const int c = wn * 32 + ni * 8 + ((lane & 3) << 1) + c2;
                        const bool ok = !diag || (c <= r);
                        if (ok) mx = fmaxf(mx, acc[mi][ni][2 * h + c2]);
                    }
                }
                mx = fmaxf(mx, __shfl_xor_sync(0xffffffffu, mx, 1));
                mx = fmaxf(mx, __shfl_xor_sync(0xffffffffu, mx, 2));
                if ((lane & 3) == 0) red[wn * 128 + r] = mx;
            }
        }
        __syncthreads();
        if (tid < 128)
            srow[tid] = fmaxf(fmaxf(red[tid], red[128 + tid]),
                              fmaxf(red[256 + tid], red[384 + tid]));
        __syncthreads();
#pragma unroll
        for (int mi = 0; mi < 4; mi++) {
#pragma unroll
            for (int h = 0; h < 2; h++) {
                const int r = wm * 64 + mi * 16 + (lane >> 2) + 8 * h;
                const float m = srow[r];
                float sum = 0.f;
#pragma unroll
                for (int ni = 0; ni < 4; ni++) {
#pragma unroll
                    for (int c2 = 0; c2 < 2; c2++) {
                        const int c = wn * 32 + ni * 8 + ((lane & 3) << 1) + c2;
                        const bool ok = !diag || (c <= r);
                        const float e = ok ? __expf(acc[mi][ni][2 * h + c2] - m) : 0.f;
                        acc[mi][ni][2 * h + c2] = e;
                        sum += e;
                    }
                }
                sum += __shfl_xor_sync(0xffffffffu, sum, 1);
                sum += __shfl_xor_sync(0xffffffffu, sum, 2);
                if ((lane & 3) == 0) red[wn * 128 + r] = sum;
            }
        }
        __syncthreads();
        if (tid < 128) {
            const float l = red[tid] + red[128 + tid] + red[256 + tid] + red[384 + tid];
            const int q = by * BM + tid;
            pm[((size_t)bz * T + q) * NTILE + bx] = srow[tid];
            pl[((size_t)bz * T + q) * NTILE + bx] = l;
        }
    }

    // ---- store ----
#pragma unroll
    for (int mi = 0; mi < 4; mi++) {
#pragma unroll
        for (int ni = 0; ni < 4; ni++) {
            const int row = by * BM + wm * 64 + mi * 16 + (lane >> 2);
            const int col = bx * BN + wn * 32 + ni * 8 + ((lane & 3) << 1);
            float v0 = acc[mi][ni][0], v1 = acc[mi][ni][1];
            float v2 = acc[mi][ni][2], v3 = acc[mi][ni][3];
            if (MODE == 2) {
                if (bz == 0) { v0 *= 0.03125f; v1 *= 0.03125f; v2 *= 0.03125f; v3 *= 0.03125f; }
                v0 = tf32r(v0); v1 = tf32r(v1); v2 = tf32r(v2); v3 = tf32r(v3);
                if (bz == 2) {   // Vt: [D][MQKV], transposed store
                    C2[(size_t)col * MQKV + row]           = v0;
                    C2[(size_t)(col + 1) * MQKV + row]     = v1;
                    C2[(size_t)col * MQKV + row + 8]       = v2;
                    C2[(size_t)(col + 1) * MQKV + row + 8] = v3;
                } else {
                    float* Cd = (bz == 0) ? C0 : C1;
                    *reinterpret_cast<float2*>(Cd + (size_t)row * ldc + col) = make_float2(v0, v1);
                    *reinterpret_cast<float2*>(Cd + (size_t)(row + 8) * ldc + col) = make_float2(v2, v3);
                }
            } else {
                float* Cd = C0 + (size_t)bz * sC;
                *reinterpret_cast<float2*>(Cd + (size_t)row * ldc + col) = make_float2(v0, v1);
                *reinterpret_cast<float2*>(Cd + (size_t)(row + 8) * ldc + col) = make_float2(v2, v3);
            }
        }
    }
}

// ---------------------------------------------------------------------------
// elementwise tf32 rounding (float4)
// ---------------------------------------------------------------------------
__global__ void __launch_bounds__(256)
round_tf32_kernel(const float* __restrict__ in, float* __restrict__ out, int n4) {
    int i = blockIdx.x * 256 + threadIdx.x;
    if (i >= n4) return;
    float4 v = reinterpret_cast<const float4*>(in)[i];
    v.x = tf32r(v.x); v.y = tf32r(v.y); v.z = tf32r(v.z); v.w = tf32r(v.w);
    reinterpret_cast<float4*>(out)[i] = v;
}

// ---------------------------------------------------------------------------
// rescale: merge per-tile softmax partials; P *= exp(m_t - m)/l; tf32 round.
// One block per row; touches only live tiles [0, qtile].
// ---------------------------------------------------------------------------
__global__ void __launch_bounds__(256)
rescale_kernel(float* __restrict__ S, const float* __restrict__ pm,
               const float* __restrict__ pl) {
    const int q = blockIdx.x, b = blockIdx.y;
    const int qt = q >> 7;                          // last live 128-tile
    __shared__ float sscale[NTILE];
    const int tid = threadIdx.x;

    if (tid < 32) {
        const size_t base = ((size_t)b * T + q) * NTILE;
        float myPm = (tid <= qt) ? pm[base + tid] : -3.4e38f;
        float myPl = (tid <= qt) ? pl[base + tid] : 0.f;
        float m = myPm;
#pragma unroll
        for (int o = 16; o; o >>= 1) m = fmaxf(m, __shfl_xor_sync(0xffffffffu, m, o));
        float e = myPl * __expf(myPm - m);
#pragma unroll
        for (int o = 16; o; o >>= 1) e += __shfl_xor_sync(0xffffffffu, e, o);
        if (tid < NTILE) sscale[tid] = __expf(myPm - m) / e;
    }
    __syncthreads();

    float4* row = reinterpret_cast<float4*>(S + ((size_t)b * T + q) * T);
    const int n4 = (qt + 1) * 32;                   // live float4 count
    for (int i = tid; i < n4; i += 256) {
        const float s = sscale[i >> 5];
        float4 v = row[i];
        v.x = tf32r(v.x * s); v.y = tf32r(v.y * s);
        v.z = tf32r(v.z * s); v.w = tf32r(v.w * s);
        row[i] = v;
    }
}

// ---------------------------------------------------------------------------
// launch
// ---------------------------------------------------------------------------
extern "C" void kernel_launch(void* const* d_in, const int* in_sizes, int n_in,
                              void* d_out, int out_size) {
    const float* X  = (const float*)d_in[0];
    const float* Wq = (const float*)d_in[1];
    const float* Wk = (const float*)d_in[2];
    const float* Wv = (const float*)d_in[3];
    float* out = (float*)d_out;

    float *Xr, *Wqr, *Wkr, *Wvr, *Qp, *Kp, *Vtp, *Sp, *pmp, *plp;
    cudaGetSymbolAddress((void**)&Xr, g_Xr);
    cudaGetSymbolAddress((void**)&Wqr, g_Wq);
    cudaGetSymbolAddress((void**)&Wkr, g_Wk);
    cudaGetSymbolAddress((void**)&Wvr, g_Wv);
    cudaGetSymbolAddress((void**)&Qp, g_Q);
    cudaGetSymbolAddress((void**)&Kp, g_K);
    cudaGetSymbolAddress((void**)&Vtp, g_Vt);
    cudaGetSymbolAddress((void**)&Sp, g_S);
    cudaGetSymbolAddress((void**)&pmp, g_pm);
    cudaGetSymbolAddress((void**)&plp, g_pl);

    cudaFuncSetAttribute(tc_gemm<0>, cudaFuncAttributeMaxDynamicSharedMemorySize, SMEM_TOTAL);
    cudaFuncSetAttribute(tc_gemm<1>, cudaFuncAttributeMaxDynamicSharedMemorySize, SMEM_TOTAL);
    cudaFuncSetAttribute(tc_gemm<2>, cudaFuncAttributeMaxDynamicSharedMemorySize, SMEM_TOTAL);

    // tf32-exact operands
    const int nX4 = MQKV * D / 4, nW4 = D * D / 4;
    round_tf32_kernel<<<(nX4 + 255) / 256, 256>>>(X, Xr, nX4);
    round_tf32_kernel<<<(nW4 + 255) / 256, 256>>>(Wq, Wqr, nW4);
    round_tf32_kernel<<<(nW4 + 255) / 256, 256>>>(Wk, Wkr, nW4);
    round_tf32_kernel<<<(nW4 + 255) / 256, 256>>>(Wv, Wvr, nW4);

    // QKV projections (bz = 0:Q, 1:K, 2:Vt), pure GEMM
    dim3 gp(D / BN, MQKV / BM, 3);
    tc_gemm<2><<<gp, NT, SMEM_TOTAL>>>(
        Xr, Wqr, Wkr, Wvr, Qp, Kp, Vtp, nullptr, nullptr,
        D, D, D, D, 0, 0, 0);

    // S tiles: P_t = exp(QK^T - m_tile), partial stats
    dim3 gs(T / BN, T / BM, BATCH);
    tc_gemm<0><<<gs, NT, SMEM_TOTAL>>>(
        Qp, Kp, nullptr, nullptr, Sp, nullptr, nullptr, pmp, plp,
        D, D, D, T,
        (long long)T * D, (long long)T * D, (long long)T * T);

    // merge + rescale P (memory-bound, live tiles only)
    dim3 gr(T, BATCH);
    rescale_kernel<<<gr, 256>>>(Sp, pmp, plp);

    // out = P V (pure GEMM, causal K extent)
    dim3 gv(D / BN, T / BM, BATCH);
    tc_gemm<1><<<gv, NT, SMEM_TOTAL>>>(
        Sp, Vtp, nullptr, nullptr, out, nullptr, nullptr, nullptr, nullptr,
        T, T, MQKV, D,
        (long long)T * T, (long long)T, (long long)T * D);
}

// round 10
// speedup vs baseline: 1.9422x; 1.7107x over previous
#include <cuda_runtime.h>
#include <cuda_fp16.h>
#include <cstdint>

// ---------------------------------------------------------------------------
// SelfAttention B=4, T=2048, D=1024, causal — fp16-operand / f32-accum edition.
// fp16 mantissa (10 bits) == tf32 mantissa, but m16n8k16 HMMA = 2x tf32 rate.
//   cvt(X), cvt(W) -> fp16 operands
//   Proj: Q = Xh Wq^T / 32 ; K = Xh Wk^T ; Vt = (Xh Wv^T)^T   (fp16 outputs)
//   S-GEMM (causal tiles): P_t = exp(S - m_tile) (fp16) + (m,l) f32 partials
//   Rescale: merge partials; P *= exp(m_t-m)/l (fp16 in place)
//   PV-GEMM: out(f32) = P V, causal K extent.
// GEMM core: 128x128x(BK=64 fp16) tiles, 3-stage cp.async, XOR-swizzled smem,
// ldmatrix.x4.b16, m16n8k16 f16 MMA (f32 acc), 8 warps, 2 CTAs/SM.
// ---------------------------------------------------------------------------

namespace {
constexpr int BATCH = 4;
constexpr int T     = 2048;
constexpr int D     = 1024;
constexpr int MQKV  = BATCH * T;          // 8192
constexpr int NTILE = T / 128;            // 16

constexpr int BM = 128, BN = 128, BK = 64;   // BK fp16 = 128 B rows
constexpr int STG = 3;
constexpr int NT  = 256;                      // 8 warps

constexpr int A_STG = BM * 128;               // 16384 B
constexpr int B_STG = BN * 128;               // 16384 B
constexpr int STG_BYTES = A_STG + B_STG;      // 32768 B
constexpr int SMEM_TOTAL = STG * STG_BYTES;   // 98304 B
}

// scratch (device globals — allocation-free)
__device__ __half g_Xh[(size_t)MQKV * D];
__device__ __half g_Wq[(size_t)D * D];
__device__ __half g_Wk[(size_t)D * D];
__device__ __half g_Wv[(size_t)D * D];
__device__ __half g_Q [(size_t)MQKV * D];
__device__ __half g_K [(size_t)MQKV * D];
__device__ __half g_Vt[(size_t)D * MQKV];                 // V transposed [D][B*T]
__device__ __half g_S [(size_t)BATCH * T * T];            // P_t (fp16)
__device__ float  g_pm[(size_t)BATCH * T * NTILE];        // per-tile row max
__device__ float  g_pl[(size_t)BATCH * T * NTILE];        // per-tile row sumexp

// ---------------------------------------------------------------------------
// helpers
// ---------------------------------------------------------------------------
__device__ __forceinline__ uint32_t smem_u32(const void* p) {
    uint32_t a;
    asm("{ .reg .u64 t; cvta.to.shared.u64 t, %1; cvt.u32.u64 %0, t; }" : "=r"(a) : "l"(p));
    return a;
}

__device__ __forceinline__ void cp16s(uint32_t s, const void* g) {
    asm volatile("cp.async.cg.shared.global [%0], [%1], 16;" ::"r"(s), "l"(g));
}
__device__ __forceinline__ void cp_commit() { asm volatile("cp.async.commit_group;"); }
__device__ __forceinline__ void cp_wait1()  { asm volatile("cp.async.wait_group 1;"); }

__device__ __forceinline__ void ldsm4(uint32_t& r0, uint32_t& r1, uint32_t& r2,
                                      uint32_t& r3, uint32_t addr) {
    asm volatile("ldmatrix.sync.aligned.m8n8.x4.shared.b16 {%0,%1,%2,%3}, [%4];"
                 : "=r"(r0), "=r"(r1), "=r"(r2), "=r"(r3) : "r"(addr));
}

// fp16 MMA, f32 accumulate: m16n8k16
__device__ __forceinline__ void mma16(float* c, const uint32_t* a, const uint32_t* b) {
    asm volatile(
        "mma.sync.aligned.m16n8k16.row.col.f32.f16.f16.f32 "
        "{%0,%1,%2,%3}, {%4,%5,%6,%7}, {%8,%9}, {%0,%1,%2,%3};"
        : "+f"(c[0]), "+f"(c[1]), "+f"(c[2]), "+f"(c[3])
        : "r"(a[0]), "r"(a[1]), "r"(a[2]), "r"(a[3]), "r"(b[0]), "r"(b[1]));
}

// ---------------------------------------------------------------------------
// TN GEMM (fp16 operands, f32 acc):  C[m,n] = sum_k A[m,k] * B[n,k]
//   MODE 0: S = QK^T, causal tile skip; epilogue exp + partials; C fp16
//   MODE 1: out = P Vt^T, causal K extent; C fp32
//   MODE 2: QKV projection; bz routes output (fp16); bz==2 -> transposed Vt
// ---------------------------------------------------------------------------
template <int MODE>
__global__ void __launch_bounds__(NT, 2)
tc_gemm(const __half* __restrict__ A,
        const __half* __restrict__ B0, const __half* __restrict__ B1,
        const __half* __restrict__ B2,
        void* __restrict__ C0, void* __restrict__ C1, void* __restrict__ C2,
        float* __restrict__ pm, float* __restrict__ pl,
        int K, int lda, int ldb, int ldc,
        long long sA, long long sB, long long sC) {
    const int bx = blockIdx.x, by = blockIdx.y, bz = blockIdx.z;
    if (MODE == 0 && bx > by) return;            // causal tile skip
    if (MODE == 1) K = (by + 1) * BM;            // causal K extent

    extern __shared__ char smem[];
    const uint32_t sb = smem_u32(smem);
    __shared__ float red[4 * 128];               // MODE 0 reductions
    __shared__ float srow[128];

    const int tid = threadIdx.x, w = tid >> 5, lane = tid & 31;
    const int wm = w >> 2, wn = w & 3;           // 2 x 4 warps, 64x32 each

    const __half* Bsel = (MODE == 2) ? (bz == 0 ? B0 : bz == 1 ? B1 : B2) : B0;
    const __half* Ab = A + (size_t)bz * sA + (size_t)by * BM * lda;
    const __half* Bb = Bsel + (size_t)bz * sB + (size_t)bx * BN * ldb;

    // cp.async per-thread pattern: row = idx>>3 (128B rows, 8 x 16B segs)
    const int cr = tid >> 3, cc = tid & 7;
    const uint32_t c_sw = (uint32_t)(cc * 16) ^ ((uint32_t)(cr & 7) << 4);

    // ldmatrix per-lane geometry (8x8 b16 tiles; 16B segs within 128B rows)
    const int l7 = lane & 7, lb3 = (lane >> 3) & 1, lb4 = (lane >> 4) & 1;
    const uint32_t xr = (uint32_t)l7 << 4;
    const uint32_t aRow0 = (uint32_t)(wm * 64 + lb3 * 8 + l7) * 128;
    const uint32_t aSeg  = (uint32_t)lb4 * 16;
    const uint32_t bRow0 = (uint32_t)(wn * 32 + lb4 * 8 + l7) * 128;
    const uint32_t bSeg  = (uint32_t)lb3 * 16;

    float acc[4][4][4];
#pragma unroll
    for (int i = 0; i < 4; i++)
#pragma unroll
        for (int j = 0; j < 4; j++)
#pragma unroll
            for (int k = 0; k < 4; k++) acc[i][j][k] = 0.f;

    auto ldst = [&](int slot, int kt) {
        const uint32_t stg = sb + slot * STG_BYTES;
        const __half* ag = Ab + kt * BK;
#pragma unroll
        for (int i = 0; i < 4; i++) {
            int r = cr + i * 32;
            cp16s(stg + (uint32_t)r * 128 + c_sw, ag + (size_t)r * lda + cc * 8);
        }
        const __half* bg = Bb + kt * BK;
#pragma unroll
        for (int i = 0; i < 4; i++) {
            int r = cr + i * 32;
            cp16s(stg + A_STG + (uint32_t)r * 128 + c_sw, bg + (size_t)r * ldb + cc * 8);
        }
    };

    const int nkt = K / BK;
    ldst(0, 0); cp_commit();
    if (nkt > 1) ldst(1, 1);
    cp_commit();

    int slot = 0;
    for (int kt = 0; kt < nkt; kt++) {
        cp_wait1();
        __syncthreads();
        if (kt + 2 < nkt) {
            int ns = slot + 2; if (ns >= STG) ns -= STG;
            ldst(ns, kt + 2);
        }
        cp_commit();

        const uint32_t astg = sb + slot * STG_BYTES;
        const uint32_t bstg = astg + A_STG;
#pragma unroll
        for (int kk4 = 0; kk4 < 128; kk4 += 32) {       // 4 x k16 slices (32B each)
            uint32_t af[4][4], bf[4][2];
            const uint32_t aoff = ((uint32_t)kk4 | aSeg) ^ xr;
            const uint32_t boff = ((uint32_t)kk4 | bSeg) ^ xr;
#pragma unroll
            for (int mi = 0; mi < 4; mi++)
                ldsm4(af[mi][0], af[mi][1], af[mi][2], af[mi][3],
                      astg + aRow0 + (uint32_t)mi * 2048 + aoff);
#pragma unroll
            for (int nj = 0; nj < 2; nj++) {
                uint32_t r0, r1, r2, r3;
                ldsm4(r0, r1, r2, r3, bstg + bRow0 + (uint32_t)nj * 2048 + boff);
                bf[nj * 2][0] = r0; bf[nj * 2][1] = r1;
                bf[nj * 2 + 1][0] = r2; bf[nj * 2 + 1][1] = r3;
            }
#pragma unroll
            for (int mi = 0; mi < 4; mi++)
#pragma unroll
                for (int ni = 0; ni < 4; ni++) mma16(acc[mi][ni], af[mi], bf[ni]);
        }
        __syncthreads();
        if (++slot == STG) slot = 0;
    }

    // ---- MODE 0 epilogue: per-row tile max / sumexp, exp-transform acc ----
    if (MODE == 0) {
        const bool diag = (bx == by);
#pragma unroll
        for (int mi = 0; mi < 4; mi++) {
#pragma unroll
            for (int h = 0; h < 2; h++) {
                const int r = wm * 64 + mi * 16 + (lane >> 2) + 8 * h;
                float mx = -3.4e38f;
#pragma unroll
                for (int ni = 0; ni < 4; ni++) {
#pragma unroll
                    for (int c2 = 0; c2 < 2; c2++) {
                        const int c = wn * 32 + ni * 8 + ((lane & 3) << 1) + c2;
                        const bool ok = !diag || (c <= r);
                        if (ok) mx = fmaxf(mx, acc[mi][ni][2 * h + c2]);
                    }
                }
                mx = fmaxf(mx, __shfl_xor_sync(0xffffffffu, mx, 1));
                mx = fmaxf(mx, __shfl_xor_sync(0xffffffffu, mx, 2));
                if ((lane & 3) == 0) red[wn * 128 + r] = mx;
            }
        }
        __syncthreads();
        if (tid < 128)
            srow[tid] = fmaxf(fmaxf(red[tid], red[128 + tid]),
                              fmaxf(red[256 + tid], red[384 + tid]));
        __syncthreads();
#pragma unroll
        for (int mi = 0; mi < 4; mi++) {
#pragma unroll
            for (int h = 0; h < 2; h++) {
                const int r = wm * 64 + mi * 16 + (lane >> 2) + 8 * h;
                const float m = srow[r];
                float sum = 0.f;
#pragma unroll
                for (int ni = 0; ni < 4; ni++) {
#pragma unroll
                    for (int c2 = 0; c2 < 2; c2++) {
                        const int c = wn * 32 + ni * 8 + ((lane & 3) << 1) + c2;
                        const bool ok = !diag || (c <= r);
                        const float e = ok ? __expf(acc[mi][ni][2 * h + c2] - m) : 0.f;
                        acc[mi][ni][2 * h + c2] = e;
                        sum += e;
                    }
                }
                sum += __shfl_xor_sync(0xffffffffu, sum, 1);
                sum += __shfl_xor_sync(0xffffffffu, sum, 2);
                if ((lane & 3) == 0) red[wn * 128 + r] = sum;
            }
        }
        __syncthreads();
        if (tid < 128) {
            const float l = red[tid] + red[128 + tid] + red[256 + tid] + red[384 + tid];
            const int q = by * BM + tid;
            pm[((size_t)bz * T + q) * NTILE + bx] = srow[tid];
            pl[((size_t)bz * T + q) * NTILE + bx] = l;
        }
    }

    // ---- store ----
#pragma unroll
    for (int mi = 0; mi < 4; mi++) {
#pragma unroll
        for (int ni = 0; ni < 4; ni++) {
            const int row = by * BM + wm * 64 + mi * 16 + (lane >> 2);
            const int col = bx * BN + wn * 32 + ni * 8 + ((lane & 3) << 1);
            float v0 = acc[mi][ni][0], v1 = acc[mi][ni][1];
            float v2 = acc[mi][ni][2], v3 = acc[mi][ni][3];
            if (MODE == 2) {
                if (bz == 0) { v0 *= 0.03125f; v1 *= 0.03125f; v2 *= 0.03125f; v3 *= 0.03125f; }
                if (bz == 2) {   // Vt: [D][MQKV], transposed fp16 store
                    __half* Cv = (__half*)C2;
                    Cv[(size_t)col * MQKV + row]           = __float2half_rn(v0);
                    Cv[(size_t)(col + 1) * MQKV + row]     = __float2half_rn(v1);
                    Cv[(size_t)col * MQKV + row + 8]       = __float2half_rn(v2);
                    Cv[(size_t)(col + 1) * MQKV + row + 8] = __float2half_rn(v3);
                } else {
                    __half* Cd = (__half*)(bz == 0 ? C0 : C1);
                    *reinterpret_cast<__half2*>(Cd + (size_t)row * ldc + col) =
                        __floats2half2_rn(v0, v1);
                    *reinterpret_cast<__half2*>(Cd + (size_t)(row + 8) * ldc + col) =
                        __floats2half2_rn(v2, v3);
                }
            } else if (MODE == 0) {
                __half* Cd = (__half*)C0 + (size_t)bz * sC;
                *reinterpret_cast<__half2*>(Cd + (size_t)row * ldc + col) =
                    __floats2half2_rn(v0, v1);
                *reinterpret_cast<__half2*>(Cd + (size_t)(row + 8) * ldc + col) =
                    __floats2half2_rn(v2, v3);
            } else {
                float* Cd = (float*)C0 + (size_t)bz * sC;
                *reinterpret_cast<float2*>(Cd + (size_t)row * ldc + col) = make_float2(v0, v1);
                *reinterpret_cast<float2*>(Cd + (size_t)(row + 8) * ldc + col) = make_float2(v2, v3);
            }
        }
    }
}

// ---------------------------------------------------------------------------
// elementwise fp32 -> fp16 conversion (float4 in, 2x half2 out)
// ---------------------------------------------------------------------------
__global__ void __launch_bounds__(256)
cvt_f16_kernel(const float* __restrict__ in, __half* __restrict__ out, int n4) {
    int i = blockIdx.x * 256 + threadIdx.x;
    if (i >= n4) return;
    float4 v = reinterpret_cast<const float4*>(in)[i];
    __half2* o = reinterpret_cast<__half2*>(out) + i * 2;
    o[0] = __floats2half2_rn(v.x, v.y);
    o[1] = __floats2half2_rn(v.z, v.w);
}

// ---------------------------------------------------------------------------
// rescale: merge per-tile softmax partials; P(fp16) *= exp(m_t - m)/l.
// One block per row; touches only live tiles [0, qtile].
// ---------------------------------------------------------------------------
__global__ void __launch_bounds__(256)
rescale_kernel(__half* __restrict__ S, const float* __restrict__ pm,
               const float* __restrict__ pl) {
    const int q = blockIdx.x, b = blockIdx.y;
    const int qt = q >> 7;                          // last live 128-tile
    __shared__ float sscale[NTILE];
    const int tid = threadIdx.x;

    if (tid < 32) {
        const size_t base = ((size_t)b * T + q) * NTILE;
        float myPm = (tid <= qt) ? pm[base + tid] : -3.4e38f;
        float myPl = (tid <= qt) ? pl[base + tid] : 0.f;
        float m = myPm;
#pragma unroll
        for (int o = 16; o; o >>= 1) m = fmaxf(m, __shfl_xor_sync(0xffffffffu, m, o));
        float e = myPl * __expf(myPm - m);
#pragma unroll
        for (int o = 16; o; o >>= 1) e += __shfl_xor_sync(0xffffffffu, e, o);
        if (tid < NTILE) sscale[tid] = __expf(myPm - m) / e;
    }
    __syncthreads();

    __half2* row = reinterpret_cast<__half2*>(S + ((size_t)b * T + q) * T);
    const int n2 = (qt + 1) * 64;                   // live half2 count
    for (int i = tid; i < n2; i += 256) {
        const float s = sscale[i >> 6];
        float2 f = __half22float2(row[i]);
        row[i] = __floats2half2_rn(f.x * s, f.y * s);
    }
}

// ---------------------------------------------------------------------------
// launch
// ---------------------------------------------------------------------------
extern "C" void kernel_launch(void* const* d_in, const int* in_sizes, int n_in,
                              void* d_out, int out_size) {
    const float* X  = (const float*)d_in[0];
    const float* Wq = (const float*)d_in[1];
    const float* Wk = (const float*)d_in[2];
    const float* Wv = (const float*)d_in[3];
    float* out = (float*)d_out;

    __half *Xh, *Wqh, *Wkh, *Wvh, *Qp, *Kp, *Vtp, *Sp;
    float *pmp, *plp;
    cudaGetSymbolAddress((void**)&Xh, g_Xh);
    cudaGetSymbolAddress((void**)&Wqh, g_Wq);
    cudaGetSymbolAddress((void**)&Wkh, g_Wk);
    cudaGetSymbolAddress((void**)&Wvh, g_Wv);
    cudaGetSymbolAddress((void**)&Qp, g_Q);
    cudaGetSymbolAddress((void**)&Kp, g_K);
    cudaGetSymbolAddress((void**)&Vtp, g_Vt);
    cudaGetSymbolAddress((void**)&Sp, g_S);
    cudaGetSymbolAddress((void**)&pmp, g_pm);
    cudaGetSymbolAddress((void**)&plp, g_pl);

    cudaFuncSetAttribute(tc_gemm<0>, cudaFuncAttributeMaxDynamicSharedMemorySize, SMEM_TOTAL);
    cudaFuncSetAttribute(tc_gemm<1>, cudaFuncAttributeMaxDynamicSharedMemorySize, SMEM_TOTAL);
    cudaFuncSetAttribute(tc_gemm<2>, cudaFuncAttributeMaxDynamicSharedMemorySize, SMEM_TOTAL);

    // fp16 operands
    const int nX4 = MQKV * D / 4, nW4 = D * D / 4;
    cvt_f16_kernel<<<(nX4 + 255) / 256, 256>>>(X, Xh, nX4);
    cvt_f16_kernel<<<(nW4 + 255) / 256, 256>>>(Wq, Wqh, nW4);
    cvt_f16_kernel<<<(nW4 + 255) / 256, 256>>>(Wk, Wkh, nW4);
    cvt_f16_kernel<<<(nW4 + 255) / 256, 256>>>(Wv, Wvh, nW4);

    // QKV projections (bz = 0:Q, 1:K, 2:Vt)
    dim3 gp(D / BN, MQKV / BM, 3);
    tc_gemm<2><<<gp, NT, SMEM_TOTAL>>>(
        Xh, Wqh, Wkh, Wvh, Qp, Kp, Vtp, nullptr, nullptr,
        D, D, D, D, 0, 0, 0);

    // S tiles: P_t = exp(QK^T - m_tile) (fp16) + partial stats
    dim3 gs(T / BN, T / BM, BATCH);
    tc_gemm<0><<<gs, NT, SMEM_TOTAL>>>(
        Qp, Kp, nullptr, nullptr, Sp, nullptr, nullptr, pmp, plp,
        D, D, D, T,
        (long long)T * D, (long long)T * D, (long long)T * T);

    // merge + rescale P
    dim3 gr(T, BATCH);
    rescale_kernel<<<gr, 256>>>(Sp, pmp, plp);

    // out = P V (f32 out, causal K extent)
    dim3 gv(D / BN, T / BM, BATCH);
    tc_gemm<1><<<gv, NT, SMEM_TOTAL>>>(
        Sp, Vtp, nullptr, nullptr, out, nullptr, nullptr, nullptr, nullptr,
        T, T, MQKV, D,
        (long long)T * T, (long long)T, (long long)T * D);
}

// round 11
// speedup vs baseline: 1.9643x; 1.0114x over previous
#include <cuda_runtime.h>
#include <cuda_fp16.h>
#include <cstdint>

// ---------------------------------------------------------------------------
// SelfAttention B=4, T=2048, D=1024, causal — fp16 + persistent-CTA edition.
//   cvt(X), cvt(W) -> fp16 operands
//   Proj: Q = Xh Wq^T / 32 ; K = Xh Wk^T ; Vt = (Xh Wv^T)^T   (fp16 outputs)
//   S-GEMM (live causal tiles only): P_t = exp(S - m_tile) (fp16) + (m,l) partials
//   PV-GEMM: per-tile prologue merges partials; A fragments scaled via __hmul2
//            (half2, one op per reg). out(f32) = softmax(S) V.
// GEMM core: 128x128x(BK=64 fp16) tiles, 3-stage cp.async, XOR-swizzled smem,
// ldmatrix.x4.b16, m16n8k16 f16 MMA (f32 acc), 8 warps, 2 CTAs/SM.
// Persistent grid (296 CTAs) with in-kernel tile decode; PV heavy-first.
// ---------------------------------------------------------------------------

namespace {
constexpr int BATCH = 4;
constexpr int T     = 2048;
constexpr int D     = 1024;
constexpr int MQKV  = BATCH * T;          // 8192
constexpr int NTILE = T / 128;            // 16

constexpr int BM = 128, BN = 128, BK = 64;   // BK fp16 = 128 B rows
constexpr int STG = 3;
constexpr int NT  = 256;                      // 8 warps
constexpr int GRID_P = 296;                   // persistent CTAs (2 x 148 SMs)

constexpr int A_STG = BM * 128;               // 16384 B
constexpr int B_STG = BN * 128;               // 16384 B
constexpr int STG_BYTES = A_STG + B_STG;      // 32768 B
constexpr int SMEM_TOTAL = STG * STG_BYTES;   // 98304 B

constexpr int NT_S  = BATCH * (NTILE * (NTILE + 1) / 2);  // 544 live S tiles
constexpr int NT_PV = (D / BN) * NTILE * BATCH;           // 512
constexpr int NT_PJ = (D / BN) * (MQKV / BM) * 3;         // 1536
}

// scratch (device globals — allocation-free)
__device__ __half g_Xh[(size_t)MQKV * D];
__device__ __half g_Wq[(size_t)D * D];
__device__ __half g_Wk[(size_t)D * D];
__device__ __half g_Wv[(size_t)D * D];
__device__ __half g_Q [(size_t)MQKV * D];
__device__ __half g_K [(size_t)MQKV * D];
__device__ __half g_Vt[(size_t)D * MQKV];                 // V transposed [D][B*T]
__device__ __half g_S [(size_t)BATCH * T * T];            // P_t (fp16)
__device__ float  g_pm[(size_t)BATCH * T * NTILE];        // per-tile row max
__device__ float  g_pl[(size_t)BATCH * T * NTILE];        // per-tile row sumexp

// ---------------------------------------------------------------------------
// helpers
// ---------------------------------------------------------------------------
__device__ __forceinline__ uint32_t smem_u32(const void* p) {
    uint32_t a;
    asm("{ .reg .u64 t; cvta.to.shared.u64 t, %1; cvt.u32.u64 %0, t; }" : "=r"(a) : "l"(p));
    return a;
}

__device__ __forceinline__ void cp16s(uint32_t s, const void* g) {
    asm volatile("cp.async.cg.shared.global [%0], [%1], 16;" ::"r"(s), "l"(g));
}
__device__ __forceinline__ void cp_commit() { asm volatile("cp.async.commit_group;"); }
__device__ __forceinline__ void cp_wait1()  { asm volatile("cp.async.wait_group 1;"); }

__device__ __forceinline__ void ldsm4(uint32_t& r0, uint32_t& r1, uint32_t& r2,
                                      uint32_t& r3, uint32_t addr) {
    asm volatile("ldmatrix.sync.aligned.m8n8.x4.shared.b16 {%0,%1,%2,%3}, [%4];"
                 : "=r"(r0), "=r"(r1), "=r"(r2), "=r"(r3) : "r"(addr));
}

__device__ __forceinline__ void mma16(float* c, const uint32_t* a, const uint32_t* b) {
    asm volatile(
        "mma.sync.aligned.m16n8k16.row.col.f32.f16.f16.f32 "
        "{%0,%1,%2,%3}, {%4,%5,%6,%7}, {%8,%9}, {%0,%1,%2,%3};"
        : "+f"(c[0]), "+f"(c[1]), "+f"(c[2]), "+f"(c[3])
        : "r"(a[0]), "r"(a[1]), "r"(a[2]), "r"(a[3]), "r"(b[0]), "r"(b[1]));
}

__device__ __forceinline__ uint32_t hmul2u(uint32_t a, __half2 s) {
    __half2 h = *reinterpret_cast<__half2*>(&a);
    h = __hmul2(h, s);
    return *reinterpret_cast<uint32_t*>(&h);
}

// ---------------------------------------------------------------------------
// Persistent TN GEMM (fp16 operands, f32 acc):  C[m,n] = sum_k A[m,k] B[n,k]
//   MODE 0: S = QK^T over live causal tiles; epilogue exp + partials; C fp16
//   MODE 1: out = softmax(S) V; heavy-first decode; A-fragment hmul2 scaling
//   MODE 2: QKV projection; bz routes output (fp16); bz==2 -> transposed Vt
// ---------------------------------------------------------------------------
template <int MODE>
__global__ void __launch_bounds__(NT, 2)
tc_gemm(const __half* __restrict__ A,
        const __half* __restrict__ B0, const __half* __restrict__ B1,
        const __half* __restrict__ B2,
        void* __restrict__ C0, void* __restrict__ C1, void* __restrict__ C2,
        float* __restrict__ pm, float* __restrict__ pl,
        int Kbase, int lda, int ldb, int ldc,
        long long sA, long long sB, long long sC) {
    extern __shared__ char smem[];
    const uint32_t sb = smem_u32(smem);
    __shared__ float red[4 * 128];               // MODE 0 reductions
    __shared__ float srow[128];
    __shared__ float saux[NTILE * 128];          // MODE 1 scale table

    const int tid = threadIdx.x, w = tid >> 5, lane = tid & 31;
    const int wm = w >> 2, wn = w & 3;           // 2 x 4 warps, 64x32 each

    // cp.async per-thread pattern
    const int cr = tid >> 3, cc = tid & 7;
    const uint32_t c_sw = (uint32_t)(cc * 16) ^ ((uint32_t)(cr & 7) << 4);

    // ldmatrix per-lane geometry
    const int l7 = lane & 7, lb3 = (lane >> 3) & 1, lb4 = (lane >> 4) & 1;
    const uint32_t xr = (uint32_t)l7 << 4;
    const uint32_t aRow0 = (uint32_t)(wm * 64 + lb3 * 8 + l7) * 128;
    const uint32_t aSeg  = (uint32_t)lb4 * 16;
    const uint32_t bRow0 = (uint32_t)(wn * 32 + lb4 * 8 + l7) * 128;
    const uint32_t bSeg  = (uint32_t)lb3 * 16;

    const int ntiles = (MODE == 0) ? NT_S : (MODE == 1) ? NT_PV : NT_PJ;

    const __half* Ab = nullptr;
    const __half* Bb = nullptr;

    auto ldst = [&](int slot, int kt) {
        const uint32_t stg = sb + slot * STG_BYTES;
        const __half* ag = Ab + kt * BK;
#pragma unroll
        for (int i = 0; i < 4; i++) {
            int r = cr + i * 32;
            cp16s(stg + (uint32_t)r * 128 + c_sw, ag + (size_t)r * lda + cc * 8);
        }
        const __half* bg = Bb + kt * BK;
#pragma unroll
        for (int i = 0; i < 4; i++) {
            int r = cr + i * 32;
            cp16s(stg + A_STG + (uint32_t)r * 128 + c_sw, bg + (size_t)r * ldb + cc * 8);
        }
    };

    for (int t = blockIdx.x; t < ntiles; t += gridDim.x) {
        // ---- decode tile ----
        int bx, by, bz;
        if (MODE == 0) {
            bz = t / (NT_S / BATCH);
            int i = t % (NT_S / BATCH);
            int acc0 = 0; by = 0;
            while (i >= acc0 + by + 1) { acc0 += by + 1; by++; }
            bx = i - acc0;
        } else if (MODE == 1) {
            by = (NTILE - 1) - (t >> 5);         // heavy first
            int r = t & 31; bx = r & 7; bz = r >> 3;
        } else {
            bz = t >> 9; int r = t & 511; by = r >> 3; bx = r & 7;
        }

        const int K = (MODE == 1) ? (by + 1) * BM : Kbase;
        const int nkt = K / BK;

        const __half* Bsel = (MODE == 2) ? (bz == 0 ? B0 : bz == 1 ? B1 : B2) : B0;
        Ab = A + (size_t)bz * sA + (size_t)by * BM * lda;
        Bb = Bsel + (size_t)bz * sB + (size_t)bx * BN * ldb;

        // ---- start pipeline ----
        ldst(0, 0); cp_commit();
        if (nkt > 1) ldst(1, 1);
        cp_commit();

        // ---- MODE 1: build per-row scale table ----
        if (MODE == 1) {
            if (tid < 128) {
                const int q = by * BM + tid;
                const float* pmr = pm + ((size_t)bz * T + q) * NTILE;
                const float* plr = pl + ((size_t)bz * T + q) * NTILE;
                float m = -3.4e38f;
                for (int tx = 0; tx <= by; tx++) m = fmaxf(m, pmr[tx]);
                float l = 0.f;
                for (int tx = 0; tx <= by; tx++) l += plr[tx] * __expf(pmr[tx] - m);
                const float il = 1.f / l;
                for (int tx = 0; tx <= by; tx++)
                    saux[tx * 128 + tid] = __expf(pmr[tx] - m) * il;
            }
            __syncthreads();
        }

        float acc[4][4][4];
#pragma unroll
        for (int i = 0; i < 4; i++)
#pragma unroll
            for (int j = 0; j < 4; j++)
#pragma unroll
                for (int k = 0; k < 4; k++) acc[i][j][k] = 0.f;

        __half2 sc0[4], sc1[4];                  // MODE 1 hoisted scales
        int slot = 0;
        for (int kt = 0; kt < nkt; kt++) {
            cp_wait1();
            __syncthreads();
            if (kt + 2 < nkt) {
                int ns = slot + 2; if (ns >= STG) ns -= STG;
                ldst(ns, kt + 2);
            }
            cp_commit();

            if (MODE == 1 && (kt & 1) == 0) {    // new 128-token P tile
                const int tx = kt >> 1;
#pragma unroll
                for (int mi = 0; mi < 4; mi++) {
                    const int ar = wm * 64 + mi * 16 + (lane >> 2);
                    sc0[mi] = __float2half2_rn(saux[tx * 128 + ar]);
                    sc1[mi] = __float2half2_rn(saux[tx * 128 + ar + 8]);
                }
            }

            const uint32_t astg = sb + slot * STG_BYTES;
            const uint32_t bstg = astg + A_STG;
#pragma unroll
            for (int kk4 = 0; kk4 < 128; kk4 += 32) {   // 4 x k16 slices
                uint32_t af[4][4], bf[4][2];
                const uint32_t aoff = ((uint32_t)kk4 | aSeg) ^ xr;
                const uint32_t boff = ((uint32_t)kk4 | bSeg) ^ xr;
#pragma unroll
                for (int mi = 0; mi < 4; mi++) {
                    ldsm4(af[mi][0], af[mi][1], af[mi][2], af[mi][3],
                          astg + aRow0 + (uint32_t)mi * 2048 + aoff);
                    if (MODE == 1) {
                        af[mi][0] = hmul2u(af[mi][0], sc0[mi]);
                        af[mi][2] = hmul2u(af[mi][2], sc0[mi]);
                        af[mi][1] = hmul2u(af[mi][1], sc1[mi]);
                        af[mi][3] = hmul2u(af[mi][3], sc1[mi]);
                    }
                }
#pragma unroll
                for (int nj = 0; nj < 2; nj++) {
                    uint32_t r0, r1, r2, r3;
                    ldsm4(r0, r1, r2, r3, bstg + bRow0 + (uint32_t)nj * 2048 + boff);
                    bf[nj * 2][0] = r0; bf[nj * 2][1] = r1;
                    bf[nj * 2 + 1][0] = r2; bf[nj * 2 + 1][1] = r3;
                }
#pragma unroll
                for (int mi = 0; mi < 4; mi++)
#pragma unroll
                    for (int ni = 0; ni < 4; ni++) mma16(acc[mi][ni], af[mi], bf[ni]);
            }
            __syncthreads();
            if (++slot == STG) slot = 0;
        }

        // ---- MODE 0 epilogue: per-row tile max / sumexp, exp-transform acc ----
        if (MODE == 0) {
            const bool diag = (bx == by);
#pragma unroll
            for (int mi = 0; mi < 4; mi++) {
#pragma unroll
                for (int h = 0; h < 2; h++) {
                    const int r = wm * 64 + mi * 16 + (lane >> 2) + 8 * h;
                    float mx = -3.4e38f;
#pragma unroll
                    for (int ni = 0; ni < 4; ni++) {
#pragma unroll
                        for (int c2 = 0; c2 < 2; c2++) {
                            const int c = wn * 32 + ni * 8 + ((lane & 3) << 1) + c2;
                            const bool ok = !diag || (c <= r);
                            if (ok) mx = fmaxf(mx, acc[mi][ni][2 * h + c2]);
                        }
                    }
                    mx = fmaxf(mx, __shfl_xor_sync(0xffffffffu, mx, 1));
                    mx = fmaxf(mx, __shfl_xor_sync(0xffffffffu, mx, 2));
                    if ((lane & 3) == 0) red[wn * 128 + r] = mx;
                }
            }
            __syncthreads();
            if (tid < 128)
                srow[tid] = fmaxf(fmaxf(red[tid], red[128 + tid]),
                                  fmaxf(red[256 + tid], red[384 + tid]));
            __syncthreads();
#pragma unroll
            for (int mi = 0; mi < 4; mi++) {
#pragma unroll
                for (int h = 0; h < 2; h++) {
                    const int r = wm * 64 + mi * 16 + (lane >> 2) + 8 * h;
                    const float m = srow[r];
                    float sum = 0.f;
#pragma unroll
                    for (int ni = 0; ni < 4; ni++) {
#pragma unroll
                        for (int c2 = 0; c2 < 2; c2++) {
                            const int c = wn * 32 + ni * 8 + ((lane & 3) << 1) + c2;
                            const bool ok = !diag || (c <= r);
                            const float e = ok ? __expf(acc[mi][ni][2 * h + c2] - m) : 0.f;
                            acc[mi][ni][2 * h + c2] = e;
                            sum += e;
                        }
                    }
                    sum += __shfl_xor_sync(0xffffffffu, sum, 1);
                    sum += __shfl_xor_sync(0xffffffffu, sum, 2);
                    if ((lane & 3) == 0) red[wn * 128 + r] = sum;
                }
            }
            __syncthreads();
            if (tid < 128) {
                const float l = red[tid] + red[128 + tid] + red[256 + tid] + red[384 + tid];
                const int q = by * BM + tid;
                pm[((size_t)bz * T + q) * NTILE + bx] = srow[tid];
                pl[((size_t)bz * T + q) * NTILE + bx] = l;
            }
            __syncthreads();                      // red/srow reused next tile
        }

        // ---- store ----
#pragma unroll
        for (int mi = 0; mi < 4; mi++) {
#pragma unroll
            for (int ni = 0; ni < 4; ni++) {
                const int row = by * BM + wm * 64 + mi * 16 + (lane >> 2);
                const int col = bx * BN + wn * 32 + ni * 8 + ((lane & 3) << 1);
                float v0 = acc[mi][ni][0], v1 = acc[mi][ni][1];
                float v2 = acc[mi][ni][2], v3 = acc[mi][ni][3];
                if (MODE == 2) {
                    if (bz == 0) { v0 *= 0.03125f; v1 *= 0.03125f; v2 *= 0.03125f; v3 *= 0.03125f; }
                    if (bz == 2) {   // Vt: [D][MQKV], transposed fp16 store
                        __half* Cv = (__half*)C2;
                        Cv[(size_t)col * MQKV + row]           = __float2half_rn(v0);
                        Cv[(size_t)(col + 1) * MQKV + row]     = __float2half_rn(v1);
                        Cv[(size_t)col * MQKV + row + 8]       = __float2half_rn(v2);
                        Cv[(size_t)(col + 1) * MQKV + row + 8] = __float2half_rn(v3);
                    } else {
                        __half* Cd = (__half*)(bz == 0 ? C0 : C1);
                        *reinterpret_cast<__half2*>(Cd + (size_t)row * ldc + col) =
                            __floats2half2_rn(v0, v1);
                        *reinterpret_cast<__half2*>(Cd + (size_t)(row + 8) * ldc + col) =
                            __floats2half2_rn(v2, v3);
                    }
                } else if (MODE == 0) {
                    __half* Cd = (__half*)C0 + (size_t)bz * sC;
                    *reinterpret_cast<__half2*>(Cd + (size_t)row * ldc + col) =
                        __floats2half2_rn(v0, v1);
                    *reinterpret_cast<__half2*>(Cd + (size_t)(row + 8) * ldc + col) =
                        __floats2half2_rn(v2, v3);
                } else {
                    float* Cd = (float*)C0 + (size_t)bz * sC;
                    *reinterpret_cast<float2*>(Cd + (size_t)row * ldc + col) = make_float2(v0, v1);
                    *reinterpret_cast<float2*>(Cd + (size_t)(row + 8) * ldc + col) = make_float2(v2, v3);
                }
            }
        }
        if (MODE == 1) __syncthreads();           // saux reused next tile
    }
}

// ---------------------------------------------------------------------------
// elementwise fp32 -> fp16 conversion
// ---------------------------------------------------------------------------
__global__ void __launch_bounds__(256)
cvt_f16_kernel(const float* __restrict__ in, __half* __restrict__ out, int n4) {
    int i = blockIdx.x * 256 + threadIdx.x;
    if (i >= n4) return;
    float4 v = reinterpret_cast<const float4*>(in)[i];
    __half2* o = reinterpret_cast<__half2*>(out) + i * 2;
    o[0] = __floats2half2_rn(v.x, v.y);
    o[1] = __floats2half2_rn(v.z, v.w);
}

// ---------------------------------------------------------------------------
// launch
// ---------------------------------------------------------------------------
extern "C" void kernel_launch(void* const* d_in, const int* in_sizes, int n_in,
                              void* d_out, int out_size) {
    const float* X  = (const float*)d_in[0];
    const float* Wq = (const float*)d_in[1];
    const float* Wk = (const float*)d_in[2];
    const float* Wv = (const float*)d_in[3];
    float* out = (float*)d_out;

    __half *Xh, *Wqh, *Wkh, *Wvh, *Qp, *Kp, *Vtp, *Sp;
    float *pmp, *plp;
    cudaGetSymbolAddress((void**)&Xh, g_Xh);
    cudaGetSymbolAddress((void**)&Wqh, g_Wq);
    cudaGetSymbolAddress((void**)&Wkh, g_Wk);
    cudaGetSymbolAddress((void**)&Wvh, g_Wv);
    cudaGetSymbolAddress((void**)&Qp, g_Q);
    cudaGetSymbolAddress((void**)&Kp, g_K);
    cudaGetSymbolAddress((void**)&Vtp, g_Vt);
    cudaGetSymbolAddress((void**)&Sp, g_S);
    cudaGetSymbolAddress((void**)&pmp, g_pm);
    cudaGetSymbolAddress((void**)&plp, g_pl);

    cudaFuncSetAttribute(tc_gemm<0>, cudaFuncAttributeMaxDynamicSharedMemorySize, SMEM_TOTAL);
    cudaFuncSetAttribute(tc_gemm<1>, cudaFuncAttributeMaxDynamicSharedMemorySize, SMEM_TOTAL);
    cudaFuncSetAttribute(tc_gemm<2>, cudaFuncAttributeMaxDynamicSharedMemorySize, SMEM_TOTAL);

    // fp16 operands
    const int nX4 = MQKV * D / 4, nW4 = D * D / 4;
    cvt_f16_kernel<<<(nX4 + 255) / 256, 256>>>(X, Xh, nX4);
    cvt_f16_kernel<<<(nW4 + 255) / 256, 256>>>(Wq, Wqh, nW4);
    cvt_f16_kernel<<<(nW4 + 255) / 256, 256>>>(Wk, Wkh, nW4);
    cvt_f16_kernel<<<(nW4 + 255) / 256, 256>>>(Wv, Wvh, nW4);

    // QKV projections (persistent)
    tc_gemm<2><<<GRID_P, NT, SMEM_TOTAL>>>(
        Xh, Wqh, Wkh, Wvh, Qp, Kp, Vtp, nullptr, nullptr,
        D, D, D, D, 0, 0, 0);

    // S tiles: P_t = exp(QK^T - m_tile) (fp16) + partial stats (persistent)
    tc_gemm<0><<<GRID_P, NT, SMEM_TOTAL>>>(
        Qp, Kp, nullptr, nullptr, Sp, nullptr, nullptr, pmp, plp,
        D, D, D, T,
        (long long)T * D, (long long)T * D, (long long)T * T);

    // out = softmax(S) V  (persistent, heavy-first, fused scaling)
    tc_gemm<1><<<GRID_P, NT, SMEM_TOTAL>>>(
        Sp, Vtp, nullptr, nullptr, out, nullptr, nullptr, pmp, plp,
        T, T, MQKV, D,
        (long long)T * T, (long long)T, (long long)T * D);
}